// round 16
// baseline (speedup 1.0000x reference)
#include <cuda_runtime.h>
#include <math.h>
#include <float.h>

#define NB 4
#define NP 4096
#define ND 768
#define NK 8
#define NH 128
#define NS 64
#define NHG 64
#define NRG 16
#define LNEPS 1e-5f
#define GC 12
#define NCELL (GC*GC*GC)
#define INVW (12.0f/5.0f)

typedef unsigned long long u64;

// f32x2 packed math (Blackwell sm_103a)
#define FMA2(acc, a, b) asm("fma.rn.f32x2 %0, %1, %2, %0;" : "+l"(acc) : "l"(a), "l"(b))
__device__ __forceinline__ u64 pack2(float lo, float hi) {
    u64 r; asm("mov.b64 %0, {%1, %2};" : "=l"(r) : "f"(lo), "f"(hi)); return r;
}
__device__ __forceinline__ float2 unpack2(u64 v) {
    float2 f; asm("mov.b64 {%0, %1}, %2;" : "=f"(f.x), "=f"(f.y) : "l"(v)); return f;
}

// hT bank swizzle
#define SWZ(j, pk) ((pk) ^ ((((j) >> 3) & 7) << 2))

// ---- scratch (no allocations allowed) ----
__device__ float g_sums16[NRG*NB*NS*ND];
__device__ float g_cnt16 [NRG*NB*NS];
__device__ float g_cnt   [NB*NS];
__device__ float g_agg   [NB*NS*ND];
__device__ int   g_knn   [NB*NP*NK];
__device__ float g_G     [NHG*NHG];
__device__ __align__(16) u64 g_GP [NHG*32];
__device__ float g_u     [NHG];
__device__ float g_c     [NHG];
__device__ float g_sb2;
__device__ float g_bm;
__device__ float g_hbar  [NB*NP*NHG];
__device__ float g_S1    [NB*NP];
__device__ float g_S2    [NB*NP];
__device__ __align__(16) u64 g_W2P [NHG*384];
__device__ float g_A1T   [NH*ND];
__device__ int   g_cellstart[NB*(NCELL+1)];
__device__ float4 g_scoord  [NB*NP];

// ---------------------------------------------------------------------------
__device__ __forceinline__ float red512(float v, float* red, int t) {
    red[t] = v; __syncthreads();
    if (t < 256) red[t] += red[t+256]; __syncthreads();
    if (t < 128) red[t] += red[t+128]; __syncthreads();
    if (t <  64) red[t] += red[t+ 64]; __syncthreads();
    if (t <  32) {
        float s = red[t] + red[t+32];
        #pragma unroll
        for (int o = 16; o; o >>= 1) s += __shfl_xor_sync(0xffffffffu, s, o);
        if (t == 0) red[0] = s;
    }
    __syncthreads();
    float r = red[0];
    __syncthreads();
    return r;
}

__device__ __forceinline__ int cell_of(float x) {
    int c = (int)(x * INVW);
    return min(GC-1, max(0, c));
}

// ---------------------------------------------------------------------------
// FUSED front-end: [0,192) seg, [192,256) prep, [256,320) W2 pack,
//                  [320,448) A1 transpose, [448,452) grid build
// ---------------------------------------------------------------------------
__global__ __launch_bounds__(512) void k_pre(
    const float* __restrict__ coords, const float* __restrict__ feat,
    const int* __restrict__ lab,
    const float* __restrict__ W2, const float* __restrict__ b2,
    const float* __restrict__ A1)
{
    extern __shared__ char sm_raw[];
    const int bx = blockIdx.x;
    const int t  = threadIdx.x;

    if (bx < 192) {
        // ============== SEG role ==========================================
        float* bins = (float*)sm_raw;
        int*   slab = (int*)(bins + NS*256);
        int*   scnt = slab + 256;
        int chunk = bx >> 6;
        int rem   = bx & 63;
        int rg    = rem >> 2;
        int b     = rem & 3;

        for (int i = t; i < NS*256; i += 512) bins[i] = 0.f;
        if (t < 256) slab[t] = lab[b*NP + rg*256 + t];
        if (t >= 256 && t < 256+64) scnt[t-256] = 0;
        __syncthreads();

        if (t < 256) {
            int d = chunk*256 + t;
            const float* fb = feat + ((size_t)(b*NP + rg*256))*ND + d;
            #pragma unroll 1
            for (int pp = 0; pp < 256; pp += 4) {
                int l0 = slab[pp+0], l1 = slab[pp+1], l2 = slab[pp+2], l3 = slab[pp+3];
                float v0 = fb[(size_t)(pp+0)*ND];
                float v1 = fb[(size_t)(pp+1)*ND];
                float v2 = fb[(size_t)(pp+2)*ND];
                float v3 = fb[(size_t)(pp+3)*ND];
                bins[l0*256 + t] += v0;
                bins[l1*256 + t] += v1;
                bins[l2*256 + t] += v2;
                bins[l3*256 + t] += v3;
            }
        } else if (chunk == 0) {
            atomicAdd(&scnt[slab[t-256]], 1);
        }
        __syncthreads();

        if (t < 256) {
            int d = chunk*256 + t;
            #pragma unroll 1
            for (int l = 0; l < NS; l++)
                g_sums16[(((size_t)rg*NB + b)*NS + l)*ND + d] = bins[l*256 + t];
        }
        if (chunk == 0 && t < NS)
            g_cnt16[(rg*NB + b)*NS + t] = (float)scnt[t];

    } else if (bx < 256) {
        // ============== PREP role: Gram row i =============================
        float* red = (float*)sm_raw;
        int i  = bx - 192;
        int j  = t & 63;
        int s8 = t >> 6;
        const float4* wi4 = (const float4*)(W2 + (size_t)i*ND + s8*96);
        const float4* wj4 = (const float4*)(W2 + (size_t)j*ND + s8*96);
        float a0 = 0.f, a1 = 0.f;
        #pragma unroll
        for (int q = 0; q < 24; q += 2) {
            float4 x0 = wi4[q],   y0 = wj4[q];
            float4 x1 = wi4[q+1], y1 = wj4[q+1];
            a0 = fmaf(x0.x,y0.x, fmaf(x0.y,y0.y, fmaf(x0.z,y0.z, fmaf(x0.w,y0.w, a0))));
            a1 = fmaf(x1.x,y1.x, fmaf(x1.y,y1.y, fmaf(x1.z,y1.z, fmaf(x1.w,y1.w, a1))));
        }
        red[t] = a0 + a1; __syncthreads();
        if (t < 256) red[t] += red[t+256]; __syncthreads();
        if (t < 128) red[t] += red[t+128]; __syncthreads();
        if (t <  64) g_G[i*NHG + t] = red[t] + red[t+64];
        __syncthreads();

        if (t < 32) {
            float lo = g_G[i*NHG + 2*t];
            float hi = g_G[i*NHG + 2*t + 1];
            g_GP[i*32 + t] = pack2(lo, hi);
        }

        const float* wi = W2 + (size_t)i*ND;
        float su = 0.f, sc = 0.f;
        for (int d = t; d < ND; d += 512) { float w = wi[d]; su += w; sc = fmaf(w, b2[d], sc); }
        float tu = red512(su, red, t);
        float tc = red512(sc, red, t);
        if (t == 0) { g_u[i] = tu * (1.f/ND); g_c[i] = tc; }

        if (i == 0) {
            float s2 = 0.f, sb = 0.f;
            for (int d = t; d < ND; d += 512) { float bv = b2[d]; s2 = fmaf(bv,bv,s2); sb += bv; }
            float t2 = red512(s2, red, t);
            float tb = red512(sb, red, t);
            if (t == 0) { g_sb2 = t2; g_bm = tb * (1.f/ND); }
        }

    } else if (bx < 320) {
        // ============== W2 PACK role ======================================
        int j = bx - 256;
        if (t < 384) {
            float lo = W2[(size_t)j*ND + t];
            float hi = W2[(size_t)j*ND + t + 384];
            g_W2P[j*384 + t] = pack2(lo, hi);
        }
    } else if (bx < 448) {
        // ============== A1 TRANSPOSE role =================================
        int r = bx - 320;            // 0..127
        for (int d = t; d < ND; d += 512)
            g_A1T[(size_t)r*ND + d] = A1[(size_t)d*NH + r];
    } else {
        // ============== GRID BUILD role (one block per batch) =============
        int b = bx - 448;
        int* cnt = (int*)sm_raw;          // 1728
        int* sc0 = cnt + NCELL;           // 2048
        int* sc1 = sc0 + 2048;            // 2048
        const float* cb = coords + (size_t)b*NP*3;

        for (int i = t; i < NCELL; i += 512) cnt[i] = 0;
        __syncthreads();

        int cid[8];
        #pragma unroll
        for (int k = 0; k < 8; k++) {
            int p = t + k*512;
            float x = cb[p*3+0], y = cb[p*3+1], z = cb[p*3+2];
            int c = (cell_of(x)*GC + cell_of(y))*GC + cell_of(z);
            cid[k] = c;
            atomicAdd(&cnt[c], 1);
        }
        __syncthreads();

        // inclusive Hillis-Steele scan over 2048 (padded)
        for (int i = t; i < 2048; i += 512) sc0[i] = (i < NCELL) ? cnt[i] : 0;
        __syncthreads();
        int* src = sc0; int* dst = sc1;
        for (int d = 1; d < 2048; d <<= 1) {
            for (int i = t; i < 2048; i += 512)
                dst[i] = src[i] + (i >= d ? src[i-d] : 0);
            __syncthreads();
            int* tmp = src; src = dst; dst = tmp;
        }
        // exclusive starts; cursor init
        for (int i = t; i < NCELL; i += 512) {
            int s = (i > 0) ? src[i-1] : 0;
            g_cellstart[b*(NCELL+1) + i] = s;
            cnt[i] = s;
        }
        if (t == 0) g_cellstart[b*(NCELL+1) + NCELL] = NP;
        __syncthreads();

        #pragma unroll
        for (int k = 0; k < 8; k++) {
            int p = t + k*512;
            float x = cb[p*3+0], y = cb[p*3+1], z = cb[p*3+2];
            int pos = atomicAdd(&cnt[cid[k]], 1);
            g_scoord[(size_t)b*NP + pos] = make_float4(x, y, z, __int_as_float(p));
        }
    }
}

// ---------------------------------------------------------------------------
// k_knn: grid-accelerated exact 8-NN, thread per query.
// phase A: 3^3 cube -> exact sorted-9 of (d2,idx) -> d9 upper bound.
// phase B: if ball(q, sqrt(d9)) not covered, rescan covering cube.
// Output identical to brute force (exact keys, exact rank).
// ---------------------------------------------------------------------------
__global__ __launch_bounds__(256) void k_knn(const float* __restrict__ coords) {
    int qi = blockIdx.x*256 + threadIdx.x;     // 0..16383
    int b  = qi >> 12, ql = qi & 4095;
    const float* cq = coords + (size_t)(b*NP + ql)*3;
    float qx = cq[0], qy = cq[1], qz = cq[2];
    int cx = cell_of(qx), cy = cell_of(qy), cz = cell_of(qz);
    const int*    cs = g_cellstart + b*(NCELL+1);
    const float4* sp = g_scoord + (size_t)b*NP;

    u64 a[9];
    int x0, x1, y0, y1, z0, z1;

    // ---- phase A: expanding cube until >=9 candidates ----
    int r = 1;
    while (true) {
        x0 = max(cx-r, 0); x1 = min(cx+r, GC-1);
        y0 = max(cy-r, 0); y1 = min(cy+r, GC-1);
        z0 = max(cz-r, 0); z1 = min(cz+r, GC-1);
        #pragma unroll
        for (int i = 0; i < 9; i++) a[i] = ~0ull;
        int scanned = 0;
        for (int xx = x0; xx <= x1; xx++)
            for (int yy = y0; yy <= y1; yy++) {
                int base = (xx*GC + yy)*GC;
                int s = cs[base + z0], e = cs[base + z1 + 1];
                scanned += e - s;
                for (int i = s; i < e; i++) {
                    float4 c = sp[i];
                    float dx = qx-c.x, dy = qy-c.y, dz = qz-c.z;
                    float d2 = fmaf(dx,dx, fmaf(dy,dy, dz*dz));
                    u64 key = ((u64)__float_as_uint(d2) << 32)
                            | (unsigned)__float_as_int(c.w);
                    if (key < a[8]) {
                        a[8] = key;
                        #pragma unroll
                        for (int p = 8; p >= 1; p--) {
                            u64 lo = (a[p] < a[p-1]) ? a[p] : a[p-1];
                            u64 hi = (a[p] < a[p-1]) ? a[p-1] : a[p];
                            a[p-1] = lo; a[p] = hi;
                        }
                    }
                }
            }
        if (scanned >= 9) break;
        r++;
    }

    // ---- phase B: cover ball(q, sqrt(d9)) ----
    float d9 = __uint_as_float((unsigned)(a[8] >> 32));
    float rT = sqrtf(d9);
    int X0 = max(0,    (int)((qx - rT) * INVW));
    int X1 = min(GC-1, (int)((qx + rT) * INVW));
    int Y0 = max(0,    (int)((qy - rT) * INVW));
    int Y1 = min(GC-1, (int)((qy + rT) * INVW));
    int Z0 = max(0,    (int)((qz - rT) * INVW));
    int Z1 = min(GC-1, (int)((qz + rT) * INVW));

    if (X0 < x0 || X1 > x1 || Y0 < y0 || Y1 > y1 || Z0 < z0 || Z1 > z1) {
        #pragma unroll
        for (int i = 0; i < 9; i++) a[i] = ~0ull;
        for (int xx = X0; xx <= X1; xx++)
            for (int yy = Y0; yy <= Y1; yy++) {
                int base = (xx*GC + yy)*GC;
                int s = cs[base + Z0], e = cs[base + Z1 + 1];
                for (int i = s; i < e; i++) {
                    float4 c = sp[i];
                    float dx = qx-c.x, dy = qy-c.y, dz = qz-c.z;
                    float d2 = fmaf(dx,dx, fmaf(dy,dy, dz*dz));
                    u64 key = ((u64)__float_as_uint(d2) << 32)
                            | (unsigned)__float_as_int(c.w);
                    if (key < a[8]) {
                        a[8] = key;
                        #pragma unroll
                        for (int p = 8; p >= 1; p--) {
                            u64 lo = (a[p] < a[p-1]) ? a[p] : a[p-1];
                            u64 hi = (a[p] < a[p-1]) ? a[p-1] : a[p];
                            a[p-1] = lo; a[p] = hi;
                        }
                    }
                }
            }
    }

    int* dst = g_knn + (size_t)qi*NK;
    #pragma unroll
    for (int k = 0; k < NK; k++)
        dst[k] = (int)(a[k+1] & 0xffffffffull);
}

// ---------------------------------------------------------------------------
// k_sa: fused stats (blocks [0,1024)) + superpoint MLP (blocks [1024,1280))
// ---------------------------------------------------------------------------
__global__ __launch_bounds__(256) void k_sa(
    const float* __restrict__ coords,
    const float* __restrict__ W1, const float* __restrict__ b1,
    const float* __restrict__ g1, const float* __restrict__ bt1,
    const float* __restrict__ ab1,
    const float* __restrict__ ag1, const float* __restrict__ abt1,
    const float* __restrict__ A2, const float* __restrict__ ab2,
    const float* __restrict__ ag2, const float* __restrict__ abt2)
{
    extern __shared__ float sm[];
    const int t = threadIdx.x;

    if (blockIdx.x >= 1024) {
        // ================= AGG role =======================================
        float* mrow = sm;
        float* ah   = mrow + 768;
        float* y2   = ah + 128;
        float* redv = y2 + 768;
        int row = blockIdx.x - 1024;
        int b = row >> 6, l = row & 63;

        if (t == 0) {
            float c = 0.f;
            #pragma unroll
            for (int r = 0; r < NRG; r++) c += g_cnt16[(r*NB + b)*NS + l];
            g_cnt[row] = c;
            redv[2] = c;
        }
        __syncthreads();
        float inv_den = 1.f / fmaxf(redv[2], 1.f);
        for (int d = t; d < ND; d += 256) {
            float s = 0.f;
            #pragma unroll
            for (int r = 0; r < NRG; r++)
                s += g_sums16[(((size_t)r*NB + b)*NS + l)*ND + d];
            mrow[d] = s * inv_den;
        }
        __syncthreads();

        {
            int o = t >> 1, half = t & 1;
            const float4* a4 = (const float4*)(g_A1T + (size_t)o*ND + half*384);
            const float4* m4 = (const float4*)(mrow + half*384);
            float a0=0.f,a1=0.f,a2=0.f,a3=0.f;
            #pragma unroll 4
            for (int q = 0; q < 96; q++) {
                float4 av = a4[q], mv = m4[q];
                a0 = fmaf(mv.x, av.x, a0);
                a1 = fmaf(mv.y, av.y, a1);
                a2 = fmaf(mv.z, av.z, a2);
                a3 = fmaf(mv.w, av.w, a3);
            }
            float acc = (a0+a1) + (a2+a3);
            acc += __shfl_xor_sync(0xffffffffu, acc, 1);
            if (!half) ah[o] = acc + ab1[o];
        }
        __syncthreads();
        if (t < 32) {
            float s = 0.f, ss = 0.f;
            #pragma unroll
            for (int q = 0; q < 4; q++) { float v = ah[t + 32*q]; s += v; ss = fmaf(v, v, ss); }
            #pragma unroll
            for (int o = 16; o; o >>= 1) { s += __shfl_xor_sync(0xffffffffu, s, o); ss += __shfl_xor_sync(0xffffffffu, ss, o); }
            if (t == 0) { float m = s*(1.f/NH); redv[0] = m; redv[1] = rsqrtf(ss*(1.f/NH) - m*m + LNEPS); }
        }
        __syncthreads();
        if (t < NH) {
            float v = fmaf((ah[t]-redv[0])*redv[1], ag1[t], abt1[t]);
            ah[t] = fmaxf(v, 0.f);
        }
        __syncthreads();

        for (int d = t; d < ND; d += 256) {
            float a0 = ab2[d], a1 = 0.f;
            #pragma unroll 4
            for (int j = 0; j < NH; j += 2) {
                a0 = fmaf(ah[j],   A2[j*ND + d],     a0);
                a1 = fmaf(ah[j+1], A2[(j+1)*ND + d], a1);
            }
            y2[d] = a0 + a1;
        }
        __syncthreads();
        if (t < 32) {
            float s = 0.f, ss = 0.f;
            #pragma unroll
            for (int q = 0; q < 24; q++) { float v = y2[t + 32*q]; s += v; ss = fmaf(v, v, ss); }
            #pragma unroll
            for (int o = 16; o; o >>= 1) { s += __shfl_xor_sync(0xffffffffu, s, o); ss += __shfl_xor_sync(0xffffffffu, ss, o); }
            if (t == 0) { float m = s*(1.f/ND); redv[0] = m; redv[1] = rsqrtf(ss*(1.f/ND) - m*m + LNEPS); }
        }
        __syncthreads();
        for (int d = t; d < ND; d += 256)
            g_agg[(size_t)row*ND + d] = fmaf((y2[d]-redv[0])*redv[1], ag2[d], abt2[d]);
        return;
    }

    // ================= STATS role =========================================
    float* hT   = sm;               // 8448
    float* sinv = hT + 8448;        // 128
    float* smn  = sinv + 128;       // 128
    float* sW1  = smn + 128;        // 256
    float* sb1  = sW1 + 256;        // 64
    float* sg1  = sb1 + 64;         // 64
    float* sbt1 = sg1 + 64;         // 64
    float* su   = sbt1 + 64;        // 64
    float* sc   = su + 64;          // 64

    const int p0 = blockIdx.x * 16;
    const int b  = blockIdx.x >> 8;

    sW1[t] = W1[t];
    if (t < 64) { sb1[t] = b1[t]; sg1[t] = g1[t]; sbt1[t] = bt1[t]; su[t] = g_u[t]; sc[t] = g_c[t]; }
    __syncthreads();

    // phase 1: geometry -> h (LN+relu)
    {
        int pk = t >> 1, jb = (t & 1) * 32;
        int p = pk >> 3, kk = pk & 7;
        int gp = p0 + p;
        int ni = g_knn[gp*NK + kk];
        const float* cq = coords + (size_t)gp*3;
        const float* cn = coords + ((size_t)b*NP + ni)*3;
        float dx = cn[0]-cq[0], dy = cn[1]-cq[1], dz = cn[2]-cq[2];
        float rd = sqrtf(fmaf(dx,dx, fmaf(dy,dy, dz*dz)));
        float gm0 = rd, gm1 = dx, gm2 = dy, gm3 = fminf(rd, 1.f);

        float hv[32];
        float s = 0.f, ss = 0.f;
        #pragma unroll
        for (int jo = 0; jo < 32; jo++) {
            int j = jb + jo;
            float v = sb1[j];
            v = fmaf(gm0, sW1[j],       v);
            v = fmaf(gm1, sW1[64 + j],  v);
            v = fmaf(gm2, sW1[128 + j], v);
            v = fmaf(gm3, sW1[192 + j], v);
            hv[jo] = v;
            s += v; ss = fmaf(v, v, ss);
        }
        s  += __shfl_xor_sync(0xffffffffu, s, 1);
        ss += __shfl_xor_sync(0xffffffffu, ss, 1);
        float m = s * (1.f/NHG);
        float iv = rsqrtf(ss*(1.f/NHG) - m*m + LNEPS);
        #pragma unroll
        for (int jo = 0; jo < 32; jo++) {
            int j = jb + jo;
            float h = fmaxf(fmaf((hv[jo]-m)*iv, sg1[j], sbt1[j]), 0.f);
            hT[j*132 + SWZ(j, pk)] = h;
        }
    }
    __syncthreads();

    // phase 2: Y = H G register-tiled (4 rows x 8 j), G via __ldg (packed)
    {
        const int jg = t & 7;
        const int rg = t >> 3;
        const int j0 = jg * 8;
        const int r0 = rg * 4;

        u64 acc[4][4];
        #pragma unroll
        for (int r = 0; r < 4; r++)
            #pragma unroll
            for (int jp = 0; jp < 4; jp++) acc[r][jp] = 0ull;

        #pragma unroll 4
        for (int k = 0; k < 64; k++) {
            float4 hv = *(const float4*)(hT + k*132 + SWZ(k, r0));
            ulonglong2 gA = __ldg((const ulonglong2*)(g_GP + k*32 + jg*4));
            ulonglong2 gB = __ldg((const ulonglong2*)(g_GP + k*32 + jg*4 + 2));
            u64 h0 = pack2(hv.x, hv.x);
            u64 h1 = pack2(hv.y, hv.y);
            u64 h2 = pack2(hv.z, hv.z);
            u64 h3 = pack2(hv.w, hv.w);
            FMA2(acc[0][0], h0, gA.x); FMA2(acc[0][1], h0, gA.y);
            FMA2(acc[0][2], h0, gB.x); FMA2(acc[0][3], h0, gB.y);
            FMA2(acc[1][0], h1, gA.x); FMA2(acc[1][1], h1, gA.y);
            FMA2(acc[1][2], h1, gB.x); FMA2(acc[1][3], h1, gB.y);
            FMA2(acc[2][0], h2, gA.x); FMA2(acc[2][1], h2, gA.y);
            FMA2(acc[2][2], h2, gB.x); FMA2(acc[2][3], h2, gB.y);
            FMA2(acc[3][0], h3, gA.x); FMA2(acc[3][1], h3, gA.y);
            FMA2(acc[3][2], h3, gB.x); FMA2(acc[3][3], h3, gB.y);
        }

        float bm = g_bm, sb2 = g_sb2;
        #pragma unroll
        for (int r = 0; r < 4; r++) {
            int row = r0 + r;
            float q = 0.f, m = 0.f, c = 0.f;
            #pragma unroll
            for (int jp = 0; jp < 4; jp++) {
                float2 y = unpack2(acc[r][jp]);
                int j = j0 + jp*2;
                float hj0 = hT[j*132 + SWZ(j, row)];
                float hj1 = hT[(j+1)*132 + SWZ(j+1, row)];
                q = fmaf(y.x, hj0, fmaf(y.y, hj1, q));
                m = fmaf(hj0, su[j], fmaf(hj1, su[j+1], m));
                c = fmaf(hj0, sc[j], fmaf(hj1, sc[j+1], c));
            }
            #pragma unroll
            for (int o = 1; o < 8; o <<= 1) {
                q += __shfl_xor_sync(0xffffffffu, q, o);
                m += __shfl_xor_sync(0xffffffffu, m, o);
                c += __shfl_xor_sync(0xffffffffu, c, o);
            }
            if (jg == 0) {
                float mm = m + bm;
                float e2 = (q + 2.f*c + sb2) * (1.f/ND);
                sinv[row] = rsqrtf(e2 - mm*mm + LNEPS);
                smn[row]  = mm;
            }
        }
    }
    __syncthreads();

    // phase 3: hbar -> global; S1/S2 -> global
    {
        #pragma unroll
        for (int qq = 0; qq < 4; qq++) {
            int o = t*4 + qq;
            int p = o >> 6;
            int j = o & 63;
            float a = 0.f;
            #pragma unroll
            for (int k = 0; k < NK; k++)
                a = fmaf(sinv[p*NK + k], hT[j*132 + SWZ(j, p*NK + k)], a);
            g_hbar[(size_t)p0*NHG + o] = a;
        }
        if (t < 16) {
            float s1 = 0.f, s2 = 0.f;
            #pragma unroll
            for (int k = 0; k < NK; k++) {
                float iv = sinv[t*NK + k];
                s1 += iv;
                s2 = fmaf(iv, smn[t*NK + k], s2);
            }
            g_S1[p0 + t] = s1;
            g_S2[p0 + t] = s2;
        }
    }
}

// ---------------------------------------------------------------------------
// k_gemm: smem-staged f32x2 GEMM, unit-stride epilogue.
// grid (256, 12): 64 points x 32 packed-d per block.
// ---------------------------------------------------------------------------
__global__ __launch_bounds__(256) void k_gemm(
    const float* __restrict__ feat, const int* __restrict__ lab,
    const float* __restrict__ b2,
    const float* __restrict__ g2, const float* __restrict__ bt2,
    float* __restrict__ out)
{
    __shared__ __align__(16) float hbars[64*64];
    __shared__ __align__(16) u64 w2c[64*32];
    __shared__ float sS1[64], sS2[64], sCnt[64];
    __shared__ int   sLab[64];
    const int t  = threadIdx.x;
    const int p0 = blockIdx.x * 64;
    const int b  = blockIdx.x >> 6;
    const int pd0 = blockIdx.y * 32;

    {
        const float4* src = (const float4*)(g_hbar + (size_t)p0*NHG);
        float4* dst = (float4*)hbars;
        #pragma unroll
        for (int i = 0; i < 4; i++) dst[t + 256*i] = src[t + 256*i];
    }
    {
        int j = t >> 2;
        int q = (t & 3) * 8;
        const ulonglong2* src = reinterpret_cast<const ulonglong2*>(g_W2P + (size_t)j*384 + pd0 + q);
        ulonglong2* dst = reinterpret_cast<ulonglong2*>(w2c + j*32 + q);
        #pragma unroll
        for (int z = 0; z < 4; z++) dst[z] = src[z];
    }
    if (t < 64) {
        int l = lab[p0 + t];
        sLab[t] = l;
        sCnt[t] = g_cnt[b*NS + l];
        sS1[t]  = g_S1[p0 + t];
        sS2[t]  = g_S2[p0 + t];
    }
    __syncthreads();

    const int pdl = t & 15;
    const int pp0 = (t >> 4) * 4;

    u64 acc[4][2];
    #pragma unroll
    for (int p = 0; p < 4; p++) { acc[p][0] = 0ull; acc[p][1] = 0ull; }

    #pragma unroll 2
    for (int k = 0; k < 64; k += 4) {
        u64 wa0 = w2c[k*32 + pdl],     wa1 = w2c[k*32 + pdl + 16];
        u64 wb0 = w2c[(k+1)*32 + pdl], wb1 = w2c[(k+1)*32 + pdl + 16];
        u64 wc0 = w2c[(k+2)*32 + pdl], wc1 = w2c[(k+2)*32 + pdl + 16];
        u64 wd0 = w2c[(k+3)*32 + pdl], wd1 = w2c[(k+3)*32 + pdl + 16];
        #pragma unroll
        for (int p = 0; p < 4; p++) {
            float4 h = *reinterpret_cast<const float4*>(hbars + (pp0+p)*64 + k);
            u64 h0 = pack2(h.x, h.x);
            u64 h1 = pack2(h.y, h.y);
            u64 h2 = pack2(h.z, h.z);
            u64 h3 = pack2(h.w, h.w);
            FMA2(acc[p][0], h0, wa0);
            FMA2(acc[p][1], h0, wa1);
            FMA2(acc[p][0], h1, wb0);
            FMA2(acc[p][1], h1, wb1);
            FMA2(acc[p][0], h2, wc0);
            FMA2(acc[p][1], h2, wc1);
            FMA2(acc[p][0], h3, wd0);
            FMA2(acc[p][1], h3, wd1);
        }
    }

    #pragma unroll
    for (int pdi = 0; pdi < 2; pdi++) {
        int d0 = pd0 + pdl + 16*pdi;
        int d1 = d0 + 384;
        float bb0 = b2[d0], gg0 = g2[d0], bt0 = bt2[d0];
        float bb1 = b2[d1], gg1 = g2[d1], bt1v = bt2[d1];
        #pragma unroll
        for (int p = 0; p < 4; p++) {
            int pl = pp0 + p;
            int gp = p0 + pl;
            bool agg_on = (sCnt[pl] >= 2.f);
            const float* ar = g_agg + ((size_t)(b*NS + sLab[pl]))*ND;
            const float* fr = feat + (size_t)gp*ND;
            float*       orow = out + (size_t)gp*ND;
            float2 dd = unpack2(acc[p][pdi]);

            float f0 = fr[d0];
            float gc0 = (dd.x + fmaf(bb0, sS1[pl], -sS2[pl])) * 0.125f;
            float e0 = agg_on ? fmaf(0.1f, ar[d0], 0.9f*f0) : f0;
            orow[d0] = fmaf(0.1f, fmaf(gc0, gg0, bt0), e0);

            float f1 = fr[d1];
            float gc1 = (dd.y + fmaf(bb1, sS1[pl], -sS2[pl])) * 0.125f;
            float e1 = agg_on ? fmaf(0.1f, ar[d1], 0.9f*f1) : f1;
            orow[d1] = fmaf(0.1f, fmaf(gc1, gg1, bt1v), e1);
        }
    }
}

// ---------------------------------------------------------------------------
extern "C" void kernel_launch(void* const* d_in, const int* in_sizes, int n_in,
                              void* d_out, int out_size) {
    const float* coords = (const float*)d_in[0];
    const float* feat   = (const float*)d_in[1];
    const int*   lab    = (const int*)  d_in[2];
    const float* W1     = (const float*)d_in[3];
    const float* b1     = (const float*)d_in[4];
    const float* g1     = (const float*)d_in[5];
    const float* bt1    = (const float*)d_in[6];
    const float* W2     = (const float*)d_in[7];
    const float* b2     = (const float*)d_in[8];
    const float* g2     = (const float*)d_in[9];
    const float* bt2    = (const float*)d_in[10];
    const float* A1     = (const float*)d_in[11];
    const float* ab1    = (const float*)d_in[12];
    const float* ag1    = (const float*)d_in[13];
    const float* abt1   = (const float*)d_in[14];
    const float* A2     = (const float*)d_in[15];
    const float* ab2    = (const float*)d_in[16];
    const float* ag2    = (const float*)d_in[17];
    const float* abt2   = (const float*)d_in[18];
    float* out = (float*)d_out;

    const int SMEM_PRE = NS*256*4 + 256*4 + 64*4;   // 66816 B (seg role max)
    const int SMEM_SA  = (8448 + 128 + 128 + 256 + 64*5) * 4;  // 37184 B
    static int smem_set = 0;
    if (!smem_set) {
        cudaFuncSetAttribute(k_pre, cudaFuncAttributeMaxDynamicSharedMemorySize, SMEM_PRE);
        cudaFuncSetAttribute(k_sa,  cudaFuncAttributeMaxDynamicSharedMemorySize, SMEM_SA);
        smem_set = 1;
    }

    k_pre <<<452, 512, SMEM_PRE>>>(coords, feat, lab, W2, b2, A1);
    k_knn <<<64, 256>>>(coords);
    k_sa  <<<1280, 256, SMEM_SA>>>(coords, W1, b1, g1, bt1,
                                   ab1, ag1, abt1, A2, ab2, ag2, abt2);
    k_gemm<<<dim3(256, 12), 256>>>(feat, lab, b2, g2, bt2, out);
}

// round 17
// speedup vs baseline: 1.1159x; 1.1159x over previous
#include <cuda_runtime.h>
#include <math.h>
#include <float.h>

#define NB 4
#define NP 4096
#define ND 768
#define NK 8
#define NH 128
#define NS 64
#define NHG 64
#define NRG 16
#define LNEPS 1e-5f

typedef unsigned long long u64;

// f32x2 packed math (Blackwell sm_103a)
#define FMA2(acc, a, b) asm("fma.rn.f32x2 %0, %1, %2, %0;" : "+l"(acc) : "l"(a), "l"(b))
__device__ __forceinline__ u64 pack2(float lo, float hi) {
    u64 r; asm("mov.b64 %0, {%1, %2};" : "=l"(r) : "f"(lo), "f"(hi)); return r;
}
__device__ __forceinline__ float2 unpack2(u64 v) {
    float2 f; asm("mov.b64 {%0, %1}, %2;" : "=f"(f.x), "=f"(f.y) : "l"(v)); return f;
}

// hT bank swizzle
#define SWZ(j, pk) ((pk) ^ ((((j) >> 3) & 7) << 2))

// ---- scratch (no allocations allowed) ----
__device__ float g_sums16[NRG*NB*NS*ND];
__device__ float g_cnt16 [NRG*NB*NS];
__device__ float g_cnt   [NB*NS];
__device__ float g_agg   [NB*NS*ND];
__device__ int   g_knn   [NB*NP*NK];
__device__ float g_G     [NHG*NHG];
__device__ __align__(16) u64 g_GP [NHG*32];
__device__ float g_u     [NHG];
__device__ float g_c     [NHG];
__device__ float g_sb2;
__device__ float g_bm;
__device__ float g_hbar  [NB*NP*NHG];
__device__ float g_S1    [NB*NP];
__device__ float g_S2    [NB*NP];
__device__ __align__(16) u64 g_W2P [NHG*384];
__device__ float g_A1T   [NH*ND];

// ---------------------------------------------------------------------------
__device__ __forceinline__ float red512(float v, float* red, int t) {
    red[t] = v; __syncthreads();
    if (t < 256) red[t] += red[t+256]; __syncthreads();
    if (t < 128) red[t] += red[t+128]; __syncthreads();
    if (t <  64) red[t] += red[t+ 64]; __syncthreads();
    if (t <  32) {
        float s = red[t] + red[t+32];
        #pragma unroll
        for (int o = 16; o; o >>= 1) s += __shfl_xor_sync(0xffffffffu, s, o);
        if (t == 0) red[0] = s;
    }
    __syncthreads();
    float r = red[0];
    __syncthreads();
    return r;
}

// ---------------------------------------------------------------------------
// FUSED front-end: [0,192) seg, [192,256) prep, [256,768) knn (2 queries/warp),
//                  [768,832) W2 pack, [832,960) A1 transpose
// ---------------------------------------------------------------------------
__global__ __launch_bounds__(512) void k_pre(
    const float* __restrict__ coords, const float* __restrict__ feat,
    const int* __restrict__ lab,
    const float* __restrict__ W2, const float* __restrict__ b2,
    const float* __restrict__ A1)
{
    extern __shared__ char sm_raw[];
    const int bx = blockIdx.x;
    const int t  = threadIdx.x;

    if (bx < 192) {
        // ============== SEG role ==========================================
        float* bins = (float*)sm_raw;
        int*   slab = (int*)(bins + NS*256);
        int*   scnt = slab + 256;
        int chunk = bx >> 6;
        int rem   = bx & 63;
        int rg    = rem >> 2;
        int b     = rem & 3;

        for (int i = t; i < NS*256; i += 512) bins[i] = 0.f;
        if (t < 256) slab[t] = lab[b*NP + rg*256 + t];
        if (t >= 256 && t < 256+64) scnt[t-256] = 0;
        __syncthreads();

        if (t < 256) {
            int d = chunk*256 + t;
            const float* fb = feat + ((size_t)(b*NP + rg*256))*ND + d;
            #pragma unroll 1
            for (int pp = 0; pp < 256; pp += 4) {
                int l0 = slab[pp+0], l1 = slab[pp+1], l2 = slab[pp+2], l3 = slab[pp+3];
                float v0 = fb[(size_t)(pp+0)*ND];
                float v1 = fb[(size_t)(pp+1)*ND];
                float v2 = fb[(size_t)(pp+2)*ND];
                float v3 = fb[(size_t)(pp+3)*ND];
                bins[l0*256 + t] += v0;
                bins[l1*256 + t] += v1;
                bins[l2*256 + t] += v2;
                bins[l3*256 + t] += v3;
            }
        } else if (chunk == 0) {
            atomicAdd(&scnt[slab[t-256]], 1);
        }
        __syncthreads();

        if (t < 256) {
            int d = chunk*256 + t;
            #pragma unroll 1
            for (int l = 0; l < NS; l++)
                g_sums16[(((size_t)rg*NB + b)*NS + l)*ND + d] = bins[l*256 + t];
        }
        if (chunk == 0 && t < NS)
            g_cnt16[(rg*NB + b)*NS + t] = (float)scnt[t];

    } else if (bx < 256) {
        // ============== PREP role: Gram row i =============================
        float* red = (float*)sm_raw;
        int i  = bx - 192;
        int j  = t & 63;
        int s8 = t >> 6;
        const float4* wi4 = (const float4*)(W2 + (size_t)i*ND + s8*96);
        const float4* wj4 = (const float4*)(W2 + (size_t)j*ND + s8*96);
        float a0 = 0.f, a1 = 0.f;
        #pragma unroll
        for (int q = 0; q < 24; q += 2) {
            float4 x0 = wi4[q],   y0 = wj4[q];
            float4 x1 = wi4[q+1], y1 = wj4[q+1];
            a0 = fmaf(x0.x,y0.x, fmaf(x0.y,y0.y, fmaf(x0.z,y0.z, fmaf(x0.w,y0.w, a0))));
            a1 = fmaf(x1.x,y1.x, fmaf(x1.y,y1.y, fmaf(x1.z,y1.z, fmaf(x1.w,y1.w, a1))));
        }
        red[t] = a0 + a1; __syncthreads();
        if (t < 256) red[t] += red[t+256]; __syncthreads();
        if (t < 128) red[t] += red[t+128]; __syncthreads();
        if (t <  64) g_G[i*NHG + t] = red[t] + red[t+64];
        __syncthreads();

        if (t < 32) {
            float lo = g_G[i*NHG + 2*t];
            float hi = g_G[i*NHG + 2*t + 1];
            g_GP[i*32 + t] = pack2(lo, hi);
        }

        const float* wi = W2 + (size_t)i*ND;
        float su = 0.f, sc = 0.f;
        for (int d = t; d < ND; d += 512) { float w = wi[d]; su += w; sc = fmaf(w, b2[d], sc); }
        float tu = red512(su, red, t);
        float tc = red512(sc, red, t);
        if (t == 0) { g_u[i] = tu * (1.f/ND); g_c[i] = tc; }

        if (i == 0) {
            float s2 = 0.f, sb = 0.f;
            for (int d = t; d < ND; d += 512) { float bv = b2[d]; s2 = fmaf(bv,bv,s2); sb += bv; }
            float t2 = red512(s2, red, t);
            float tb = red512(sb, red, t);
            if (t == 0) { g_sb2 = t2; g_bm = tb * (1.f/ND); }
        }

    } else if (bx < 768) {
        // ============== KNN role: 2 queries/warp, dot-form scores =========
        // pass 1: per-lane top-1 over two disjoint half-streams (64 subsets
        // of 64 candidates). At most 8 subset-mins < v9, so the 9-pop T is
        // still an upper bound on the true 9th-smallest. Exact rank select
        // in pass 2 is unchanged -> bit-identical knn output.
        const float SEPS = 1e-3f;
        float4* sh  = (float4*)sm_raw;                 // 16 KB (x,y,z,0.5||c||^2)
        u64*    buf = (u64*)(sm_raw + 16384);          // 16 KB
        int*    bcnt= (int*)(sm_raw + 16384 + 16384);  // 32 ints
        int qb = bx - 256;            // 0..511
        int b  = qb >> 7;             // 128 blocks per batch
        int w  = t >> 5, lane = t & 31;
        int q0 = ((qb & 127)*16 + w)*2;
        const float* cb = coords + (size_t)b*NP*3;

        float qx[2], qy[2], qz[2];
        #pragma unroll
        for (int q = 0; q < 2; q++) {
            qx[q] = -cb[(q0+q)*3+0];
            qy[q] = -cb[(q0+q)*3+1];
            qz[q] = -cb[(q0+q)*3+2];
        }

        // pass 1: per-lane top-1 per half-stream per query
        float a0[2], a1[2];
        #pragma unroll
        for (int q = 0; q < 2; q++) { a0[q] = FLT_MAX; a1[q] = FLT_MAX; }

        for (int tile = 0; tile < 4; tile++) {
            __syncthreads();
            for (int i = t; i < 1024; i += 512) {
                int jj = tile*1024 + i;
                float x = cb[jj*3+0], y = cb[jj*3+1], z = cb[jj*3+2];
                float n = 0.5f * fmaf(x,x, fmaf(y,y, z*z));
                sh[i] = make_float4(x, y, z, n);
            }
            __syncthreads();
            #pragma unroll 4
            for (int j = lane; j < 512; j += 32) {
                float4 c = sh[j];
                #pragma unroll
                for (int q = 0; q < 2; q++) {
                    float s = fmaf(qx[q], c.x, fmaf(qy[q], c.y, fmaf(qz[q], c.z, c.w)));
                    a0[q] = fminf(a0[q], s);
                }
            }
            #pragma unroll 4
            for (int j = 512 + lane; j < 1024; j += 32) {
                float4 c = sh[j];
                #pragma unroll
                for (int q = 0; q < 2; q++) {
                    float s = fmaf(qx[q], c.x, fmaf(qy[q], c.y, fmaf(qz[q], c.z, c.w)));
                    a1[q] = fminf(a1[q], s);
                }
            }
        }

        // merge: T_s[q] = 9th popped from 64-value union (>= true 9th s)
        float T[2];
        #pragma unroll
        for (int q = 0; q < 2; q++) {
            float h0 = fminf(a0[q], a1[q]);
            float h1 = fmaxf(a0[q], a1[q]);
            float Tq = 0.f;
            #pragma unroll
            for (int r = 0; r < 9; r++) {
                float m = h0;
                #pragma unroll
                for (int o = 16; o; o >>= 1)
                    m = fminf(m, __shfl_xor_sync(0xffffffffu, m, o));
                if (h0 == m) { h0 = h1; h1 = FLT_MAX; }
                Tq = m;
            }
            T[q] = Tq + SEPS;
        }

        if (lane < 2) bcnt[w*2 + lane] = 0;
        __syncwarp();

        // pass 2: filter on s; exact d2 key for accepted candidates only
        for (int tile = 0; tile < 4; tile++) {
            __syncthreads();
            for (int i = t; i < 1024; i += 512) {
                int jj = tile*1024 + i;
                float x = cb[jj*3+0], y = cb[jj*3+1], z = cb[jj*3+2];
                float n = 0.5f * fmaf(x,x, fmaf(y,y, z*z));
                sh[i] = make_float4(x, y, z, n);
            }
            __syncthreads();
            #pragma unroll 4
            for (int j = lane; j < 1024; j += 32) {
                float4 c = sh[j];
                #pragma unroll
                for (int q = 0; q < 2; q++) {
                    float s = fmaf(qx[q], c.x, fmaf(qy[q], c.y, fmaf(qz[q], c.z, c.w)));
                    if (s <= T[q]) {
                        float dx = -qx[q]-c.x, dy = -qy[q]-c.y, dz = -qz[q]-c.z;
                        float d2 = fmaf(dx,dx, fmaf(dy,dy, dz*dz));
                        int pos = atomicAdd(&bcnt[w*2+q], 1);
                        if (pos < 64)
                            buf[(w*2+q)*64 + pos] = ((u64)__float_as_uint(d2) << 32)
                                                  | (unsigned)(tile*1024 + j);
                    }
                }
            }
        }
        __syncwarp();

        // exact rank select per query (keys are exact reference d2)
        #pragma unroll
        for (int q = 0; q < 2; q++) {
            int cnt = min(bcnt[w*2+q], 64);
            const u64* bq = buf + (w*2+q)*64;
            int* dst = g_knn + ((size_t)(b*NP + q0 + q))*NK;
            #pragma unroll
            for (int sl = 0; sl < 2; sl++) {
                int s = lane + sl*32;
                if (s < cnt) {
                    u64 mine = bq[s];
                    int rank = 0;
                    for (int i = 0; i < cnt; i++)
                        rank += (bq[i] < mine) ? 1 : 0;
                    if (rank >= 1 && rank <= 8)
                        dst[rank-1] = (int)(mine & 0xffffffffull);
                }
            }
        }

    } else if (bx < 832) {
        // ============== W2 PACK role ======================================
        int j = bx - 768;
        if (t < 384) {
            float lo = W2[(size_t)j*ND + t];
            float hi = W2[(size_t)j*ND + t + 384];
            g_W2P[j*384 + t] = pack2(lo, hi);
        }
    } else {
        // ============== A1 TRANSPOSE role =================================
        int r = bx - 832;            // 0..127
        for (int d = t; d < ND; d += 512)
            g_A1T[(size_t)r*ND + d] = A1[(size_t)d*NH + r];
    }
}

// ---------------------------------------------------------------------------
// k_sa: fused agg (blocks [0,256), launched FIRST: LPT scheduling) +
//       stats (blocks [256,1280))
// ---------------------------------------------------------------------------
__global__ __launch_bounds__(256) void k_sa(
    const float* __restrict__ coords,
    const float* __restrict__ W1, const float* __restrict__ b1,
    const float* __restrict__ g1, const float* __restrict__ bt1,
    const float* __restrict__ ab1,
    const float* __restrict__ ag1, const float* __restrict__ abt1,
    const float* __restrict__ A2, const float* __restrict__ ab2,
    const float* __restrict__ ag2, const float* __restrict__ abt2)
{
    extern __shared__ float sm[];
    const int t = threadIdx.x;

    if (blockIdx.x < 256) {
        // ================= AGG role (heavy blocks first) ==================
        float* mrow = sm;
        float* ah   = mrow + 768;
        float* y2   = ah + 128;
        float* redv = y2 + 768;
        int row = blockIdx.x;
        int b = row >> 6, l = row & 63;

        if (t == 0) {
            float c = 0.f;
            #pragma unroll
            for (int r = 0; r < NRG; r++) c += g_cnt16[(r*NB + b)*NS + l];
            g_cnt[row] = c;
            redv[2] = c;
        }
        __syncthreads();
        float inv_den = 1.f / fmaxf(redv[2], 1.f);
        for (int d = t; d < ND; d += 256) {
            float s = 0.f;
            #pragma unroll
            for (int r = 0; r < NRG; r++)
                s += g_sums16[(((size_t)r*NB + b)*NS + l)*ND + d];
            mrow[d] = s * inv_den;
        }
        __syncthreads();

        {
            int o = t >> 1, half = t & 1;
            const float4* a4 = (const float4*)(g_A1T + (size_t)o*ND + half*384);
            const float4* m4 = (const float4*)(mrow + half*384);
            float a0=0.f,a1=0.f,a2=0.f,a3=0.f;
            #pragma unroll 4
            for (int q = 0; q < 96; q++) {
                float4 av = a4[q], mv = m4[q];
                a0 = fmaf(mv.x, av.x, a0);
                a1 = fmaf(mv.y, av.y, a1);
                a2 = fmaf(mv.z, av.z, a2);
                a3 = fmaf(mv.w, av.w, a3);
            }
            float acc = (a0+a1) + (a2+a3);
            acc += __shfl_xor_sync(0xffffffffu, acc, 1);
            if (!half) ah[o] = acc + ab1[o];
        }
        __syncthreads();
        if (t < 32) {
            float s = 0.f, ss = 0.f;
            #pragma unroll
            for (int q = 0; q < 4; q++) { float v = ah[t + 32*q]; s += v; ss = fmaf(v, v, ss); }
            #pragma unroll
            for (int o = 16; o; o >>= 1) { s += __shfl_xor_sync(0xffffffffu, s, o); ss += __shfl_xor_sync(0xffffffffu, ss, o); }
            if (t == 0) { float m = s*(1.f/NH); redv[0] = m; redv[1] = rsqrtf(ss*(1.f/NH) - m*m + LNEPS); }
        }
        __syncthreads();
        if (t < NH) {
            float v = fmaf((ah[t]-redv[0])*redv[1], ag1[t], abt1[t]);
            ah[t] = fmaxf(v, 0.f);
        }
        __syncthreads();

        for (int d = t; d < ND; d += 256) {
            float a0 = ab2[d], a1 = 0.f;
            #pragma unroll 4
            for (int j = 0; j < NH; j += 2) {
                a0 = fmaf(ah[j],   A2[j*ND + d],     a0);
                a1 = fmaf(ah[j+1], A2[(j+1)*ND + d], a1);
            }
            y2[d] = a0 + a1;
        }
        __syncthreads();
        if (t < 32) {
            float s = 0.f, ss = 0.f;
            #pragma unroll
            for (int q = 0; q < 24; q++) { float v = y2[t + 32*q]; s += v; ss = fmaf(v, v, ss); }
            #pragma unroll
            for (int o = 16; o; o >>= 1) { s += __shfl_xor_sync(0xffffffffu, s, o); ss += __shfl_xor_sync(0xffffffffu, ss, o); }
            if (t == 0) { float m = s*(1.f/ND); redv[0] = m; redv[1] = rsqrtf(ss*(1.f/ND) - m*m + LNEPS); }
        }
        __syncthreads();
        for (int d = t; d < ND; d += 256)
            g_agg[(size_t)row*ND + d] = fmaf((y2[d]-redv[0])*redv[1], ag2[d], abt2[d]);
        return;
    }

    // ================= STATS role =========================================
    float* hT   = sm;               // 8448
    float* sinv = hT + 8448;        // 128
    float* smn  = sinv + 128;       // 128
    float* sW1  = smn + 128;        // 256
    float* sb1  = sW1 + 256;        // 64
    float* sg1  = sb1 + 64;         // 64
    float* sbt1 = sg1 + 64;         // 64
    float* su   = sbt1 + 64;        // 64
    float* sc   = su + 64;          // 64

    const int sb = blockIdx.x - 256;
    const int p0 = sb * 16;
    const int b  = sb >> 8;

    sW1[t] = W1[t];
    if (t < 64) { sb1[t] = b1[t]; sg1[t] = g1[t]; sbt1[t] = bt1[t]; su[t] = g_u[t]; sc[t] = g_c[t]; }
    __syncthreads();

    // phase 1: geometry -> h (LN+relu)
    {
        int pk = t >> 1, jb = (t & 1) * 32;
        int p = pk >> 3, kk = pk & 7;
        int gp = p0 + p;
        int ni = g_knn[gp*NK + kk];
        const float* cq = coords + (size_t)gp*3;
        const float* cn = coords + ((size_t)b*NP + ni)*3;
        float dx = cn[0]-cq[0], dy = cn[1]-cq[1], dz = cn[2]-cq[2];
        float rd = sqrtf(fmaf(dx,dx, fmaf(dy,dy, dz*dz)));
        float gm0 = rd, gm1 = dx, gm2 = dy, gm3 = fminf(rd, 1.f);

        float hv[32];
        float s = 0.f, ss = 0.f;
        #pragma unroll
        for (int jo = 0; jo < 32; jo++) {
            int j = jb + jo;
            float v = sb1[j];
            v = fmaf(gm0, sW1[j],       v);
            v = fmaf(gm1, sW1[64 + j],  v);
            v = fmaf(gm2, sW1[128 + j], v);
            v = fmaf(gm3, sW1[192 + j], v);
            hv[jo] = v;
            s += v; ss = fmaf(v, v, ss);
        }
        s  += __shfl_xor_sync(0xffffffffu, s, 1);
        ss += __shfl_xor_sync(0xffffffffu, ss, 1);
        float m = s * (1.f/NHG);
        float iv = rsqrtf(ss*(1.f/NHG) - m*m + LNEPS);
        #pragma unroll
        for (int jo = 0; jo < 32; jo++) {
            int j = jb + jo;
            float h = fmaxf(fmaf((hv[jo]-m)*iv, sg1[j], sbt1[j]), 0.f);
            hT[j*132 + SWZ(j, pk)] = h;
        }
    }
    __syncthreads();

    // phase 2: Y = H G register-tiled (4 rows x 8 j), G via __ldg (packed)
    {
        const int jg = t & 7;
        const int rg = t >> 3;
        const int j0 = jg * 8;
        const int r0 = rg * 4;

        u64 acc[4][4];
        #pragma unroll
        for (int r = 0; r < 4; r++)
            #pragma unroll
            for (int jp = 0; jp < 4; jp++) acc[r][jp] = 0ull;

        #pragma unroll 4
        for (int k = 0; k < 64; k++) {
            float4 hv = *(const float4*)(hT + k*132 + SWZ(k, r0));
            ulonglong2 gA = __ldg((const ulonglong2*)(g_GP + k*32 + jg*4));
            ulonglong2 gB = __ldg((const ulonglong2*)(g_GP + k*32 + jg*4 + 2));
            u64 h0 = pack2(hv.x, hv.x);
            u64 h1 = pack2(hv.y, hv.y);
            u64 h2 = pack2(hv.z, hv.z);
            u64 h3 = pack2(hv.w, hv.w);
            FMA2(acc[0][0], h0, gA.x); FMA2(acc[0][1], h0, gA.y);
            FMA2(acc[0][2], h0, gB.x); FMA2(acc[0][3], h0, gB.y);
            FMA2(acc[1][0], h1, gA.x); FMA2(acc[1][1], h1, gA.y);
            FMA2(acc[1][2], h1, gB.x); FMA2(acc[1][3], h1, gB.y);
            FMA2(acc[2][0], h2, gA.x); FMA2(acc[2][1], h2, gA.y);
            FMA2(acc[2][2], h2, gB.x); FMA2(acc[2][3], h2, gB.y);
            FMA2(acc[3][0], h3, gA.x); FMA2(acc[3][1], h3, gA.y);
            FMA2(acc[3][2], h3, gB.x); FMA2(acc[3][3], h3, gB.y);
        }

        float bm = g_bm, sb2 = g_sb2;
        #pragma unroll
        for (int r = 0; r < 4; r++) {
            int row = r0 + r;
            float q = 0.f, m = 0.f, c = 0.f;
            #pragma unroll
            for (int jp = 0; jp < 4; jp++) {
                float2 y = unpack2(acc[r][jp]);
                int j = j0 + jp*2;
                float hj0 = hT[j*132 + SWZ(j, row)];
                float hj1 = hT[(j+1)*132 + SWZ(j+1, row)];
                q = fmaf(y.x, hj0, fmaf(y.y, hj1, q));
                m = fmaf(hj0, su[j], fmaf(hj1, su[j+1], m));
                c = fmaf(hj0, sc[j], fmaf(hj1, sc[j+1], c));
            }
            #pragma unroll
            for (int o = 1; o < 8; o <<= 1) {
                q += __shfl_xor_sync(0xffffffffu, q, o);
                m += __shfl_xor_sync(0xffffffffu, m, o);
                c += __shfl_xor_sync(0xffffffffu, c, o);
            }
            if (jg == 0) {
                float mm = m + bm;
                float e2 = (q + 2.f*c + sb2) * (1.f/ND);
                sinv[row] = rsqrtf(e2 - mm*mm + LNEPS);
                smn[row]  = mm;
            }
        }
    }
    __syncthreads();

    // phase 3: hbar -> global; S1/S2 -> global
    {
        #pragma unroll
        for (int qq = 0; qq < 4; qq++) {
            int o = t*4 + qq;
            int p = o >> 6;
            int j = o & 63;
            float a = 0.f;
            #pragma unroll
            for (int k = 0; k < NK; k++)
                a = fmaf(sinv[p*NK + k], hT[j*132 + SWZ(j, p*NK + k)], a);
            g_hbar[(size_t)p0*NHG + o] = a;
        }
        if (t < 16) {
            float s1 = 0.f, s2 = 0.f;
            #pragma unroll
            for (int k = 0; k < NK; k++) {
                float iv = sinv[t*NK + k];
                s1 += iv;
                s2 = fmaf(iv, smn[t*NK + k], s2);
            }
            g_S1[p0 + t] = s1;
            g_S2[p0 + t] = s2;
        }
    }
}

// ---------------------------------------------------------------------------
// k_gemm: smem-staged f32x2 GEMM, unit-stride epilogue.
// grid (256, 12): 64 points x 32 packed-d per block.
// ---------------------------------------------------------------------------
__global__ __launch_bounds__(256) void k_gemm(
    const float* __restrict__ feat, const int* __restrict__ lab,
    const float* __restrict__ b2,
    const float* __restrict__ g2, const float* __restrict__ bt2,
    float* __restrict__ out)
{
    __shared__ __align__(16) float hbars[64*64];
    __shared__ __align__(16) u64 w2c[64*32];
    __shared__ float sS1[64], sS2[64], sCnt[64];
    __shared__ int   sLab[64];
    const int t  = threadIdx.x;
    const int p0 = blockIdx.x * 64;
    const int b  = blockIdx.x >> 6;
    const int pd0 = blockIdx.y * 32;

    {
        const float4* src = (const float4*)(g_hbar + (size_t)p0*NHG);
        float4* dst = (float4*)hbars;
        #pragma unroll
        for (int i = 0; i < 4; i++) dst[t + 256*i] = src[t + 256*i];
    }
    {
        int j = t >> 2;
        int q = (t & 3) * 8;
        const ulonglong2* src = reinterpret_cast<const ulonglong2*>(g_W2P + (size_t)j*384 + pd0 + q);
        ulonglong2* dst = reinterpret_cast<ulonglong2*>(w2c + j*32 + q);
        #pragma unroll
        for (int z = 0; z < 4; z++) dst[z] = src[z];
    }
    if (t < 64) {
        int l = lab[p0 + t];
        sLab[t] = l;
        sCnt[t] = g_cnt[b*NS + l];
        sS1[t]  = g_S1[p0 + t];
        sS2[t]  = g_S2[p0 + t];
    }
    __syncthreads();

    const int pdl = t & 15;
    const int pp0 = (t >> 4) * 4;

    u64 acc[4][2];
    #pragma unroll
    for (int p = 0; p < 4; p++) { acc[p][0] = 0ull; acc[p][1] = 0ull; }

    #pragma unroll 2
    for (int k = 0; k < 64; k += 4) {
        u64 wa0 = w2c[k*32 + pdl],     wa1 = w2c[k*32 + pdl + 16];
        u64 wb0 = w2c[(k+1)*32 + pdl], wb1 = w2c[(k+1)*32 + pdl + 16];
        u64 wc0 = w2c[(k+2)*32 + pdl], wc1 = w2c[(k+2)*32 + pdl + 16];
        u64 wd0 = w2c[(k+3)*32 + pdl], wd1 = w2c[(k+3)*32 + pdl + 16];
        #pragma unroll
        for (int p = 0; p < 4; p++) {
            float4 h = *reinterpret_cast<const float4*>(hbars + (pp0+p)*64 + k);
            u64 h0 = pack2(h.x, h.x);
            u64 h1 = pack2(h.y, h.y);
            u64 h2 = pack2(h.z, h.z);
            u64 h3 = pack2(h.w, h.w);
            FMA2(acc[p][0], h0, wa0);
            FMA2(acc[p][1], h0, wa1);
            FMA2(acc[p][0], h1, wb0);
            FMA2(acc[p][1], h1, wb1);
            FMA2(acc[p][0], h2, wc0);
            FMA2(acc[p][1], h2, wc1);
            FMA2(acc[p][0], h3, wd0);
            FMA2(acc[p][1], h3, wd1);
        }
    }

    #pragma unroll
    for (int pdi = 0; pdi < 2; pdi++) {
        int d0 = pd0 + pdl + 16*pdi;
        int d1 = d0 + 384;
        float bb0 = b2[d0], gg0 = g2[d0], bt0 = bt2[d0];
        float bb1 = b2[d1], gg1 = g2[d1], bt1v = bt2[d1];
        #pragma unroll
        for (int p = 0; p < 4; p++) {
            int pl = pp0 + p;
            int gp = p0 + pl;
            bool agg_on = (sCnt[pl] >= 2.f);
            const float* ar = g_agg + ((size_t)(b*NS + sLab[pl]))*ND;
            const float* fr = feat + (size_t)gp*ND;
            float*       orow = out + (size_t)gp*ND;
            float2 dd = unpack2(acc[p][pdi]);

            float f0 = fr[d0];
            float gc0 = (dd.x + fmaf(bb0, sS1[pl], -sS2[pl])) * 0.125f;
            float e0 = agg_on ? fmaf(0.1f, ar[d0], 0.9f*f0) : f0;
            orow[d0] = fmaf(0.1f, fmaf(gc0, gg0, bt0), e0);

            float f1 = fr[d1];
            float gc1 = (dd.y + fmaf(bb1, sS1[pl], -sS2[pl])) * 0.125f;
            float e1 = agg_on ? fmaf(0.1f, ar[d1], 0.9f*f1) : f1;
            orow[d1] = fmaf(0.1f, fmaf(gc1, gg1, bt1v), e1);
        }
    }
}

// ---------------------------------------------------------------------------
extern "C" void kernel_launch(void* const* d_in, const int* in_sizes, int n_in,
                              void* d_out, int out_size) {
    const float* coords = (const float*)d_in[0];
    const float* feat   = (const float*)d_in[1];
    const int*   lab    = (const int*)  d_in[2];
    const float* W1     = (const float*)d_in[3];
    const float* b1     = (const float*)d_in[4];
    const float* g1     = (const float*)d_in[5];
    const float* bt1    = (const float*)d_in[6];
    const float* W2     = (const float*)d_in[7];
    const float* b2     = (const float*)d_in[8];
    const float* g2     = (const float*)d_in[9];
    const float* bt2    = (const float*)d_in[10];
    const float* A1     = (const float*)d_in[11];
    const float* ab1    = (const float*)d_in[12];
    const float* ag1    = (const float*)d_in[13];
    const float* abt1   = (const float*)d_in[14];
    const float* A2     = (const float*)d_in[15];
    const float* ab2    = (const float*)d_in[16];
    const float* ag2    = (const float*)d_in[17];
    const float* abt2   = (const float*)d_in[18];
    float* out = (float*)d_out;

    const int SMEM_PRE = NS*256*4 + 256*4 + 64*4;   // 66816 B (seg role max)
    const int SMEM_SA  = (8448 + 128 + 128 + 256 + 64*5) * 4;  // 37184 B
    static int smem_set = 0;
    if (!smem_set) {
        cudaFuncSetAttribute(k_pre, cudaFuncAttributeMaxDynamicSharedMemorySize, SMEM_PRE);
        cudaFuncSetAttribute(k_sa,  cudaFuncAttributeMaxDynamicSharedMemorySize, SMEM_SA);
        smem_set = 1;
    }

    k_pre <<<960, 512, SMEM_PRE>>>(coords, feat, lab, W2, b2, A1);
    k_sa  <<<1280, 256, SMEM_SA>>>(coords, W1, b1, g1, bt1,
                                   ab1, ag1, abt1, A2, ab2, ag2, abt2);
    k_gemm<<<dim3(256, 12), 256>>>(feat, lab, b2, g2, bt2, out);
}